// round 1
// baseline (speedup 1.0000x reference)
#include <cuda_runtime.h>
#include <math.h>

// ---------------- problem constants ----------------
#define BS   4
#define H    480
#define W    640
#define NC   16
#define CCH  20          // 4 + NC
#define M    480
#define VR   100
#define ZH   80
#define MINZ 9
#define MAXZ 49          // z in [9,49)
#define HWPIX (H*W)      // 307200

#define O_FPMAP 0
#define O_MAP   40000
#define O_POSE1 18472000
#define O_POSE2 18472012
#define O_TRANS 18472024

// ---------------- device scratch ----------------
// ones grid: [b][x 100][y 100][z 80]
__device__ __align__(16) float g_gridA[BS * VR * VR * ZH];            // 3.2M floats
// sem grid:  [b][x 100][y 100][z' 40][c 16]
__device__ __align__(16) float g_gridS[BS * VR * VR * 40 * 16];       // 25.6M floats
// compact maps: [b][kc 18][y 100][x 100]  (kc: 0=fp_map,1=fp_exp,2..17=cat)
__device__ __align__(16) float g_cmap[BS * 18 * VR * VR];
// rotated buffer: [b][kc 18][h 480][w 480]
__device__ __align__(16) float g_rbuf[BS * 18 * M * M];
// per-batch params: {cos(t), sin(t), stx, sty}
__device__ float4 g_params[BS];

__device__ __forceinline__ void red4(float* p, float a, float b, float c, float d) {
#if !defined(__CUDA_ARCH__) || __CUDA_ARCH__ >= 900
    asm volatile("red.global.add.v4.f32 [%0], {%1, %2, %3, %4};"
                 :: "l"(p), "f"(a), "f"(b), "f"(c), "f"(d) : "memory");
#else
    atomicAdd(p + 0, a); atomicAdd(p + 1, b);
    atomicAdd(p + 2, c); atomicAdd(p + 3, d);
#endif
}

__device__ __forceinline__ float clamp01(float v) {
    return fminf(fmaxf(v, 0.0f), 1.0f);
}

// ---------------- 1. zero scratch grids ----------------
__global__ void __launch_bounds__(256) zero_kernel() {
    int id = blockIdx.x * 256 + threadIdx.x;     // 7,200,000 float4s
    float4 z = make_float4(0.f, 0.f, 0.f, 0.f);
    if (id < 800000)      reinterpret_cast<float4*>(g_gridA)[id] = z;
    else                  reinterpret_cast<float4*>(g_gridS)[id - 800000] = z;
}

// ---------------- 2. pose math ----------------
__global__ void pose_kernel(const float* __restrict__ pose_obs,
                            const float* __restrict__ poses_last,
                            float* __restrict__ out) {
    int b = threadIdx.x;
    if (b >= BS) return;
    const float DEG = 57.29577951308232f;
    float plx = poses_last[b*3+0], ply = poses_last[b*3+1], plt = poses_last[b*3+2];
    float ox = pose_obs[b*3+0], oy = pose_obs[b*3+1], ot = pose_obs[b*3+2];
    float o = plt / DEG;
    float so = sinf(o), co = cosf(o);
    float yy = ply + ox * so + oy * co;
    float xx = plx + ox * co - oy * so;
    float tt = plt + ot * DEG;
    tt = fmodf(tt - 180.0f, 360.0f) + 180.0f;
    tt = fmodf(tt + 180.0f, 360.0f) - 180.0f;

    out[O_POSE1 + b*3 + 0] = xx;
    out[O_POSE1 + b*3 + 1] = yy;
    out[O_POSE1 + b*3 + 2] = tt;
    out[O_POSE2 + b*3 + 0] = xx;
    out[O_POSE2 + b*3 + 1] = yy;
    out[O_POSE2 + b*3 + 2] = tt;

    float half = (float)(M / 2);  // 240
    float stx = -((xx * 100.0f / 5.0f) - half) / half;
    float sty = -((yy * 100.0f / 5.0f) - half) / half;
    float t = (90.0f - tt) * (float)(3.14159265358979323846 / 180.0);
    g_params[b] = make_float4(cosf(t), sinf(t), stx, sty);
}

// ---------------- 3. voxel splat ----------------
__global__ void __launch_bounds__(256) splat_kernel(const float* __restrict__ obs,
                                                    const float* __restrict__ view_angles) {
    int id = blockIdx.x * 256 + threadIdx.x;
    if (id >= BS * HWPIX) return;
    int b   = id / HWPIX;
    int pix = id - b * HWPIX;
    int i   = pix / W;
    int j   = pix - i * W;

    const float* ob = obs + (size_t)b * CCH * HWPIX;
    float depth = ob[3 * HWPIX + pix];

    float a  = view_angles[b] * (float)(3.14159265358979323846 / 180.0);
    float ca = cosf(a), sa = sinf(a);

    const float FOC = (float)(320.0 / tan(39.5 * 3.14159265358979323846 / 180.0));
    float gx = (float)j;
    float gz = (float)(H - 1 - i);
    float Xp = (gx - 319.5f) * depth / FOC;
    float Zp = (gz - 239.5f) * depth / FOC;
    float Yv = ca * depth - sa * Zp;
    float Zv = sa * depth + ca * Zp + 155.0f;
    float Xv = Xp + 250.0f;

    float xs = (Xv / 5.0f - 50.0f) / 100.0f * 2.0f;
    float ys = (Yv / 5.0f - 50.0f) / 100.0f * 2.0f;
    float zs = (Zv / 5.0f - 32.0f) / 80.0f * 2.0f;

    float pos[3];
    pos[0] = xs * 50.0f + 50.0f;
    pos[1] = ys * 50.0f + 50.0f;
    pos[2] = zs * 40.0f + 40.0f;
    const float gd[3] = {100.0f, 100.0f, 80.0f};

    float wgt[3][2];
    int   idx[3][2];
#pragma unroll
    for (int d = 0; d < 3; d++) {
        float fl = floorf(pos[d]);
#pragma unroll
        for (int ix = 0; ix < 2; ix++) {
            float p = fl + (float)ix;
            bool safe = (p > 0.0f) && (p < gd[d]);
            wgt[d][ix] = safe ? (1.0f - fabsf(pos[d] - p)) : 0.0f;
            idx[d][ix] = safe ? (int)p : 0;
        }
    }

    // load 16 semantic channel values (coalesced across warp)
    float sem[16];
    const float* sp = ob + 4 * HWPIX + pix;
#pragma unroll
    for (int c = 0; c < 16; c++) sem[c] = sp[c * HWPIX];

    float* gA = g_gridA + (size_t)b * (VR * VR * ZH);
    float* gS = g_gridS + (size_t)b * (VR * VR * 40 * 16);

#pragma unroll
    for (int cx = 0; cx < 2; cx++) {
        float wx = wgt[0][cx];
        if (wx <= 0.0f) continue;
        int bxA = idx[0][cx] * (VR * ZH);      // *8000
        int bxS = idx[0][cx] * (VR * 40 * 16); // *64000
#pragma unroll
        for (int cy = 0; cy < 2; cy++) {
            float wxy = wx * wgt[1][cy];
            if (wxy <= 0.0f) continue;
            int byA = bxA + idx[1][cy] * ZH;       // *80
            int byS = bxS + idx[1][cy] * (40*16);  // *640
#pragma unroll
            for (int cz = 0; cz < 2; cz++) {
                float w = wxy * wgt[2][cz];
                if (w <= 0.0f) continue;
                int z = idx[2][cz];
                atomicAdd(&gA[byA + z], w);
                int zp = z - MINZ;
                if (zp >= 0 && zp < 40) {
                    float* p = &gS[byS + zp * 16];
                    red4(p,      sem[0]*w,  sem[1]*w,  sem[2]*w,  sem[3]*w);
                    red4(p + 4,  sem[4]*w,  sem[5]*w,  sem[6]*w,  sem[7]*w);
                    red4(p + 8,  sem[8]*w,  sem[9]*w,  sem[10]*w, sem[11]*w);
                    red4(p + 12, sem[12]*w, sem[13]*w, sem[14]*w, sem[15]*w);
                }
            }
        }
    }
}

// ---------------- 4. z-column reduce -> compact maps ----------------
__global__ void __launch_bounds__(128) reduce_kernel(float* __restrict__ out) {
    int id = blockIdx.x * 128 + threadIdx.x;
    if (id >= BS * VR * VR) return;
    int px = id % VR;
    int t  = id / VR;
    int py = t % VR;
    int b  = t / VR;

    const float* pa = g_gridA + ((size_t)(b * VR + px) * VR + py) * ZH;
    float s_all = 0.0f, s_mid = 0.0f;
#pragma unroll
    for (int z = 0; z < ZH; z++) {
        float v = rintf(pa[z]);
        s_all += v;
        if (z >= MINZ && z < MAXZ) s_mid += v;
    }
    float fpmap = clamp01(s_mid);   // MAP_THR = 1
    float fpexp = clamp01(s_all);   // EXP_THR = 1

    int cbase = b * 18 * (VR * VR) + py * VR + px;
    g_cmap[cbase]                 = fpmap;
    g_cmap[cbase + (VR * VR)]     = fpexp;
    out[O_FPMAP + b * (VR * VR) + py * VR + px] = fpmap;

    const float* ps = g_gridS + ((size_t)(b * VR + px) * VR + py) * (40 * 16);
    float sc[16];
#pragma unroll
    for (int c = 0; c < 16; c++) sc[c] = 0.0f;
    for (int zp = 0; zp < 40; zp++) {
#pragma unroll
        for (int c = 0; c < 16; c++) sc[c] += rintf(ps[zp * 16 + c]);
    }
#pragma unroll
    for (int c = 0; c < 16; c++)
        g_cmap[cbase + (2 + c) * (VR * VR)] = clamp01(sc[c] / 5.0f);  // CAT_THR = 5
}

// ---------------- 5. rotation grid_sample ----------------
__device__ __forceinline__ float fetch_cmap(const float* cp, int iy, int ix) {
    return (ix >= 190 && ix < 290 && iy >= 240 && iy < 340)
               ? cp[(iy - 240) * VR + (ix - 190)] : 0.0f;
}

__global__ void __launch_bounds__(256) rotate_kernel() {
    int id = blockIdx.x * 256 + threadIdx.x;    // BS*18*480*480
    int w = id % M;
    int t = id / M;
    int h = t % M;
    t /= M;
    int kc = t % 18;
    int b  = t / 18;

    float4 prm = g_params[b];
    float ct = prm.x, st = prm.y;
    float X = -1.0f + (float)w * (2.0f / 479.0f);
    float Y = -1.0f + (float)h * (2.0f / 479.0f);
    float gxn = ct * X - st * Y;
    float gyn = st * X + ct * Y;
    float x = (gxn + 1.0f) * 0.5f * 479.0f;
    float y = (gyn + 1.0f) * 0.5f * 479.0f;
    float x0f = floorf(x), y0f = floorf(y);
    int x0 = (int)x0f, y0 = (int)y0f;

    float r = 0.0f;
    if (x0 >= 189 && x0 <= 289 && y0 >= 239 && y0 <= 339) {
        float wx1 = x - x0f, wy1 = y - y0f;
        const float* cp = g_cmap + (size_t)(b * 18 + kc) * (VR * VR);
        float v00 = fetch_cmap(cp, y0,     x0);
        float v01 = fetch_cmap(cp, y0,     x0 + 1);
        float v10 = fetch_cmap(cp, y0 + 1, x0);
        float v11 = fetch_cmap(cp, y0 + 1, x0 + 1);
        r = v00 * (1.0f - wx1) * (1.0f - wy1)
          + v01 * wx1 * (1.0f - wy1)
          + v10 * (1.0f - wx1) * wy1
          + v11 * wx1 * wy1;
    }
    g_rbuf[id] = r;
}

// ---------------- 6. translation grid_sample + max fuse ----------------
__global__ void __launch_bounds__(256) translate_kernel(const float* __restrict__ maps_last,
                                                        float* __restrict__ out) {
    int id = blockIdx.x * 256 + threadIdx.x;    // BS*20*480*480
    int w = id % M;
    int t = id / M;
    int h = t % M;
    t /= M;
    int c = t % CCH;
    int b = t / CCH;

    float tr = 0.0f;
    if (c != 2 && c != 3) {
        int kc = (c < 2) ? c : c - 2;
        float4 prm = g_params[b];
        float gxn = (-1.0f + (float)w * (2.0f / 479.0f)) + prm.z;
        float gyn = (-1.0f + (float)h * (2.0f / 479.0f)) + prm.w;
        float x = (gxn + 1.0f) * 0.5f * 479.0f;
        float y = (gyn + 1.0f) * 0.5f * 479.0f;
        float x0f = floorf(x), y0f = floorf(y);
        int x0 = (int)x0f, y0 = (int)y0f;
        float wx1 = x - x0f, wy1 = y - y0f;
        const float* rp = g_rbuf + (size_t)(b * 18 + kc) * (M * M);

        float v00 = (x0   >= 0 && x0   < M && y0   >= 0 && y0   < M) ? rp[y0 * M + x0]           : 0.0f;
        float v01 = (x0+1 >= 0 && x0+1 < M && y0   >= 0 && y0   < M) ? rp[y0 * M + x0 + 1]       : 0.0f;
        float v10 = (x0   >= 0 && x0   < M && y0+1 >= 0 && y0+1 < M) ? rp[(y0+1) * M + x0]       : 0.0f;
        float v11 = (x0+1 >= 0 && x0+1 < M && y0+1 >= 0 && y0+1 < M) ? rp[(y0+1) * M + x0 + 1]   : 0.0f;

        tr = v00 * (1.0f - wx1) * (1.0f - wy1)
           + v01 * wx1 * (1.0f - wy1)
           + v10 * (1.0f - wx1) * wy1
           + v11 * wx1 * wy1;
    }
    out[O_TRANS + id] = tr;
    out[O_MAP + id]   = fmaxf(maps_last[id], tr);
}

// ---------------- launch ----------------
extern "C" void kernel_launch(void* const* d_in, const int* in_sizes, int n_in,
                              void* d_out, int out_size) {
    const float* obs         = (const float*)d_in[0];
    const float* pose_obs    = (const float*)d_in[1];
    const float* maps_last   = (const float*)d_in[2];
    const float* poses_last  = (const float*)d_in[3];
    const float* view_angles = (const float*)d_in[4];
    float* out = (float*)d_out;

    zero_kernel<<<28125, 256>>>();                         // 7.2M float4
    pose_kernel<<<1, 32>>>(pose_obs, poses_last, out);
    splat_kernel<<<(BS * HWPIX + 255) / 256, 256>>>(obs, view_angles);
    reduce_kernel<<<(BS * VR * VR + 127) / 128, 128>>>(out);
    rotate_kernel<<<(BS * 18 * M * M) / 256, 256>>>();
    translate_kernel<<<(BS * CCH * M * M) / 256, 256>>>(maps_last, out);
}